// round 14
// baseline (speedup 1.0000x reference)
#include <cuda_runtime.h>

#define C   32
#define HF  96
#define WF  192
#define DD  192
#define HOUT 384
#define WOUT 768
#define ND  48
#define CHW (HF*WF)
#define COST_ELEMS (DD*HF*WF)
#define TP  (WF + 16)          // padded t/it rows: 16 zero floats before idx 0

// ---- packed f32x2 helpers (sm_103a) ----------------------------------------
__device__ __forceinline__ unsigned long long pack2(float lo, float hi) {
    unsigned long long r;
    asm("mov.b64 %0, {%1, %2};" : "=l"(r) : "f"(lo), "f"(hi));
    return r;
}
__device__ __forceinline__ void fma2(unsigned long long& acc,
                                     unsigned long long a, unsigned long long b) {
    asm("fma.rn.f32x2 %0, %1, %2, %0;" : "+l"(acc) : "l"(a), "l"(b));
}
__device__ __forceinline__ float2 unpack2(unsigned long long v) {
    float lo, hi;
    asm("mov.b64 {%0, %1}, %2;" : "=f"(lo), "=f"(hi) : "l"(v));
    return make_float2(lo, hi);
}

// ---------------------------------------------------------------------------
// Kernel 1: cosine cost volume slice (R13 one-row shape, parameterized octs).
// Grid (96 h, 3 by), 384 threads, 54KB smem -> 2 blocks/SM.
// oct = oct_base + 3*dq + by, active while dq < ndq.
//   costA: base=0, ndq=2 -> octs 0..5  (d <  48, pred's input)
//   costB: base=6, ndq=6 -> octs 6..23 (d >= 48)
// Inactive-dq threads exit after the block-wide load/norm prologue.
// out[d,h,w] = (sum_c r[c,w]*t[c,w-d]) * ir[w] * it[w-d]; zero-padded t/it
// keep exact zeros for w < d with a single branch-free code path.
// ---------------------------------------------------------------------------
__global__ __launch_bounds__(384, 2) void cost_kernel(
    const float* __restrict__ ref, const float* __restrict__ tgt,
    float* __restrict__ out, int oct_base, int ndq)
{
    extern __shared__ float smbuf[];
    float (*r)[WF]  = reinterpret_cast<float (*)[WF]>(smbuf);            // [C][WF]
    float (*t)[TP]  = reinterpret_cast<float (*)[TP]>(smbuf + C*WF);     // [C][TP]
    float* part_r   = smbuf + C*WF + C*TP;                               // [192]
    float* part_t   = part_r + WF;                                       // [192]
    float* ir       = part_t + WF;                                       // [WF]
    float* itp      = ir + WF;                                           // [TP]

    const int h   = blockIdx.x;          // h-row 0..95
    const int by  = blockIdx.y;          // 0..2
    const int tid = threadIdx.x;         // 0..383

    // zero pads: t pad = C*16 floats (128 f4), itp pad = 16 floats (4 f4)
    if (tid < 128) {
        int c = tid / 4;
        int q = tid % 4;
        *reinterpret_cast<float4*>(&t[c][q*4]) = make_float4(0.f,0.f,0.f,0.f);
    } else if (tid < 132) {
        int q = tid - 128;
        *reinterpret_cast<float4*>(&itp[q*4]) = make_float4(0.f,0.f,0.f,0.f);
    }

    // vectorized loads: 1536 float4 per tensor (32 c x 48 quads)
    #pragma unroll
    for (int j = 0; j < 4; j++) {
        int k  = tid + j*384;            // 0..1535
        int c  = k / 48;
        int kk = k % 48;
        *reinterpret_cast<float4*>(&r[c][kk*4]) =
            *reinterpret_cast<const float4*>(ref + c*CHW + h*WF + kk*4);
        *reinterpret_cast<float4*>(&t[c][16 + kk*4]) =
            *reinterpret_cast<const float4*>(tgt + c*CHW + h*WF + kk*4);
    }
    __syncthreads();

    // inverse norms: 192 columns x 2 half-c partials (all 12 warps active)
    {
        int w    = tid % WF;
        int half = tid / WF;             // 0 or 1
        float sr = 0.f, st = 0.f;
        int cbase = half * 16;
        #pragma unroll
        for (int c = 0; c < 16; c++) {
            float a = r[cbase + c][w];      sr = fmaf(a, a, sr);
            float b = t[cbase + c][16 + w]; st = fmaf(b, b, st);
        }
        if (half) { part_r[w] = sr; part_t[w] = st; }
        __syncthreads();
        if (!half) {
            ir[w]       = rsqrtf(sr + part_r[w] + 1e-12f);
            itp[16 + w] = rsqrtf(st + part_t[w] + 1e-12f);
        }
    }
    __syncthreads();

    // one 4w x 8d tile per thread: 48 wq x ndq dq tiles
    const int wq = tid % 48;
    const int dq = tid / 48;             // 0..7
    if (dq >= ndq) return;               // inactive slot for this launch
    const int w0 = wq * 4;
    const int d0 = 8 * (oct_base + 3*dq + by);

    unsigned long long axy0[8], azw0[8]; // (x,y)/(z,w) packed accs per i
    #pragma unroll
    for (int i = 0; i < 8; i++) { axy0[i] = 0ULL; azw0[i] = 0ULL; }

    const int pb = 16 + w0 - d0 - 8;     // padded window base (mult of 4)

    if (w0 - d0 >= 0) {
        for (int c = 0; c < C; c++) {
            float4 a  = *reinterpret_cast<const float4*>(&r[c][w0]);
            float4 v0 = *reinterpret_cast<const float4*>(&t[c][pb]);
            float4 v1 = *reinterpret_cast<const float4*>(&t[c][pb + 4]);
            float4 v2 = *reinterpret_cast<const float4*>(&t[c][pb + 8]);
            float e[12] = {v0.x, v0.y, v0.z, v0.w,
                           v1.x, v1.y, v1.z, v1.w,
                           v2.x, v2.y, v2.z, v2.w};
            unsigned long long pxy = pack2(a.x, a.y);
            unsigned long long pzw = pack2(a.z, a.w);
            #pragma unroll
            for (int j = 1; j <= 10; j++) {
                unsigned long long P = pack2(e[j], e[j+1]);
                if (j <= 8) fma2(axy0[8 - j], pxy, P);
                if (j >= 3) fma2(azw0[10 - j], pzw, P);
            }
        }
        float4 irq = *reinterpret_cast<const float4*>(&ir[w0]);
        float4 s0 = *reinterpret_cast<const float4*>(&itp[pb]);
        float4 s1 = *reinterpret_cast<const float4*>(&itp[pb + 4]);
        float4 s2 = *reinterpret_cast<const float4*>(&itp[pb + 8]);
        float e[12] = {s0.x, s0.y, s0.z, s0.w,
                       s1.x, s1.y, s1.z, s1.w,
                       s2.x, s2.y, s2.z, s2.w};
        #pragma unroll
        for (int i = 0; i < 8; i++) {
            float2 xy = unpack2(axy0[i]);
            float2 zw = unpack2(azw0[i]);
            float4 o;
            o.x = xy.x * irq.x * e[8  - i];
            o.y = xy.y * irq.y * e[9  - i];
            o.z = zw.x * irq.z * e[10 - i];
            o.w = zw.y * irq.w * e[11 - i];
            *reinterpret_cast<float4*>(&out[((d0 + i)*HF + h)*WF + w0]) = o;
        }
    } else {
        float4 z = make_float4(0.f, 0.f, 0.f, 0.f);
        #pragma unroll
        for (int i = 0; i < 8; i++)
            *reinterpret_cast<float4*>(&out[((d0 + i)*HF + h)*WF + w0]) = z;
    }
}

// ---------------------------------------------------------------------------
// Kernel 2: fused trilinear upsample + argmax + clamp(.,1).
// EXACT R7/R12/R13 version (the consistently-best pred).
// ---------------------------------------------------------------------------
#define SSTR 52

__device__ __forceinline__ float bilin1(const float* __restrict__ c00,
                                        const float* __restrict__ c01,
                                        const float* __restrict__ c10,
                                        const float* __restrict__ c11,
                                        int d, float fw, float fh)
{
    float t0 = fmaf(fw, c01[d] - c00[d], c00[d]);
    float t1 = fmaf(fw, c11[d] - c10[d], c10[d]);
    return fmaf(fh, t1 - t0, t0);
}

__device__ __forceinline__ void chunk8(const float* __restrict__ c00,
                                       const float* __restrict__ c01,
                                       const float* __restrict__ c10,
                                       const float* __restrict__ c11,
                                       int dbase, float fw, float fh,
                                       float* __restrict__ s)
{
    #pragma unroll
    for (int half = 0; half < 2; half++) {
        float4 v00 = *reinterpret_cast<const float4*>(c00 + dbase + half*4);
        float4 v01 = *reinterpret_cast<const float4*>(c01 + dbase + half*4);
        float4 v10 = *reinterpret_cast<const float4*>(c10 + dbase + half*4);
        float4 v11 = *reinterpret_cast<const float4*>(c11 + dbase + half*4);
        float t0, t1;
        t0 = fmaf(fw, v01.x - v00.x, v00.x);
        t1 = fmaf(fw, v11.x - v10.x, v10.x);
        s[half*4+0] = fmaf(fh, t1 - t0, t0);
        t0 = fmaf(fw, v01.y - v00.y, v00.y);
        t1 = fmaf(fw, v11.y - v10.y, v10.y);
        s[half*4+1] = fmaf(fh, t1 - t0, t0);
        t0 = fmaf(fw, v01.z - v00.z, v00.z);
        t1 = fmaf(fw, v11.z - v10.z, v10.z);
        s[half*4+2] = fmaf(fh, t1 - t0, t0);
        t0 = fmaf(fw, v01.w - v00.w, v00.w);
        t1 = fmaf(fw, v11.w - v10.w, v10.w);
        s[half*4+3] = fmaf(fh, t1 - t0, t0);
    }
}

__device__ __forceinline__ void scan_head(const float* __restrict__ s,
                                          float& best, int& bestE)
{
    #pragma unroll
    for (int e = 0; e < 7; e++) {
        float nb = (e == 0) ? s[1] : fmaxf(s[e-1], s[e+1]);
        float cand = fmaf(7.0f, s[e], nb);
        if (cand > best) { best = cand; bestE = e; }
    }
}

__device__ __forceinline__ void scan_mid(const float* __restrict__ p,
                                         const float* __restrict__ c,
                                         int qb, float& best, int& bestE)
{
    {   float nb = fmaxf(p[6], c[0]);
        float cand = fmaf(7.0f, p[7], nb);
        if (cand > best) { best = cand; bestE = qb - 1; } }
    {   float nb = fmaxf(p[7], c[1]);
        float cand = fmaf(7.0f, c[0], nb);
        if (cand > best) { best = cand; bestE = qb; } }
    #pragma unroll
    for (int j = 1; j < 7; j++) {
        float nb = fmaxf(c[j-1], c[j+1]);
        float cand = fmaf(7.0f, c[j], nb);
        if (cand > best) { best = cand; bestE = qb + j; }
    }
}

__global__ __launch_bounds__(256) void pred_kernel(
    const float* __restrict__ cost, float* __restrict__ pred)
{
    __shared__ float sc[4][10][SSTR];
    const int tx = threadIdx.x, ty = threadIdx.y;
    const int tid = ty*32 + tx;
    const int hb = 2*(int)blockIdx.y - 1;
    const int wb = 8*(int)blockIdx.x - 1;

    #pragma unroll
    for (int it = 0; it < 8; it++) {
        int i = tid + it * 256;
        if (i < 4*10*ND) {
            int wc = i % 10;
            int hr = (i / 10) % 4;
            int d  = i / 40;
            int hh = min(max(hb + hr, 0), HF - 1);
            int ww = min(max(wb + wc, 0), WF - 1);
            sc[hr][wc][d] = cost[(d*HF + hh)*WF + ww];
        }
    }
    __syncthreads();

    const int wo = blockIdx.x*32 + tx;
    const int ho = blockIdx.y*8 + ty;

    float xh = fminf(fmaxf(0.25f*(float)ho - 0.375f, 0.f), (float)(HF - 1));
    int   h0 = min((int)xh, HF - 2);
    float fh = xh - (float)h0;
    float xw = fminf(fmaxf(0.25f*(float)wo - 0.375f, 0.f), (float)(WF - 1));
    int   w0 = min((int)xw, WF - 2);
    float fw = xw - (float)w0;

    const int lh = h0 - hb;
    const int lw = w0 - wb;
    const float* c00 = &sc[lh][lw][0];
    const float* c01 = &sc[lh][lw+1][0];
    const float* c10 = &sc[lh+1][lw][0];
    const float* c11 = &sc[lh+1][lw+1][0];

    float sA[8], sB[8];
    float best;
    int bestE = -1;                      // -1 => k = 0

    chunk8(c00, c01, c10, c11, 0, fw, fh, sA);
    best = 8.0f * sA[0];                 // exact sample s[0] (scaled)
    scan_head(sA, best, bestE);

    chunk8(c00, c01, c10, c11,  8, fw, fh, sB); scan_mid(sA, sB,  8, best, bestE);
    chunk8(c00, c01, c10, c11, 16, fw, fh, sA); scan_mid(sB, sA, 16, best, bestE);
    chunk8(c00, c01, c10, c11, 24, fw, fh, sB); scan_mid(sA, sB, 24, best, bestE);
    chunk8(c00, c01, c10, c11, 32, fw, fh, sA); scan_mid(sB, sA, 32, best, bestE);
    chunk8(c00, c01, c10, c11, 40, fw, fh, sB); scan_mid(sA, sB, 40, best, bestE);

    {   // e = 47
        float nb = sB[6];
        float cand = fmaf(7.0f, sB[7], nb);
        if (cand > best) { best = cand; bestE = 47; }
    }
    float s47 = sB[7];

    int k;
    if (8.0f * s47 > best) {
        k = 4*(ND-1) + 2;                   // 190: exact sample s[47]
    } else if (bestE < 0) {
        k = 0;
    } else {
        float smL = -3.0e38f, smR = -3.0e38f;
        if (bestE > 0)      smL = bilin1(c00, c01, c10, c11, bestE - 1, fw, fh);
        if (bestE < ND - 1) smR = bilin1(c00, c01, c10, c11, bestE + 1, fw, fh);
        k = 4*bestE + 1 + ((smR > smL) ? 1 : 0);   // tie -> left (smaller k)
    }
    k = max(k, 1);
    pred[ho*WOUT + wo] = (float)k;
}

// ---------------------------------------------------------------------------
// Launch topology: costA (d<48) runs alone on the full chip; then costB
// (d>=48) and pred run CONCURRENTLY — costB (2x54KB blocks, 24 warps/SM)
// and pred (8KB, 8-warp blocks) co-reside per SM, pred warps filling costB's
// issue bubbles. Fork/join uses the standard capturable event pattern.
// ---------------------------------------------------------------------------
static cudaStream_t g_s2;
static cudaEvent_t  g_e0, g_e1;
static struct _StreamInit {
    _StreamInit() {
        cudaStreamCreateWithFlags(&g_s2, cudaStreamNonBlocking);
        cudaEventCreateWithFlags(&g_e0, cudaEventDisableTiming);
        cudaEventCreateWithFlags(&g_e1, cudaEventDisableTiming);
    }
} g_stream_init;

extern "C" void kernel_launch(void* const* d_in, const int* in_sizes, int n_in,
                              void* d_out, int out_size)
{
    const float* left  = (const float*)d_in[0];
    const float* right = (const float*)d_in[1];
    float* out = (float*)d_out;

    const int smem_bytes =
        (C*WF + C*TP + WF + WF + WF + TP) * (int)sizeof(float);   // ~54 KB
    cudaFuncSetAttribute(cost_kernel,
                         cudaFuncAttributeMaxDynamicSharedMemorySize, smem_bytes);

    dim3 gc(HF, 3), bc(384);

    // costA: octs 0..5 (d < 48) — full chip, feeds pred
    cost_kernel<<<gc, bc, smem_bytes>>>(left, right, out, 0, 2);

    // fork: costB waits for costA, then runs concurrently with pred
    cudaEventRecord(g_e0, 0);
    cudaStreamWaitEvent(g_s2, g_e0, 0);
    cost_kernel<<<gc, bc, smem_bytes, g_s2>>>(left, right, out, 6, 6);

    // pred: main stream, ordered after costA only
    dim3 g2(WOUT/32, HOUT/8), b2(32, 8);
    pred_kernel<<<g2, b2>>>(out, out + COST_ELEMS);

    // join: main stream waits for costB before returning
    cudaEventRecord(g_e1, g_s2);
    cudaStreamWaitEvent(0, g_e1, 0);
}

// round 15
// speedup vs baseline: 1.0401x; 1.0401x over previous
#include <cuda_runtime.h>

#define C   32
#define HF  96
#define WF  192
#define DD  192
#define HOUT 384
#define WOUT 768
#define ND  48
#define CHW (HF*WF)
#define COST_ELEMS (DD*HF*WF)
#define TP  (WF + 16)          // padded t/it rows: 16 zero floats before idx 0

// ---- packed f32x2 helpers (sm_103a) ----------------------------------------
__device__ __forceinline__ unsigned long long pack2(float lo, float hi) {
    unsigned long long r;
    asm("mov.b64 %0, {%1, %2};" : "=l"(r) : "f"(lo), "f"(hi));
    return r;
}
__device__ __forceinline__ void fma2(unsigned long long& acc,
                                     unsigned long long a, unsigned long long b) {
    asm("fma.rn.f32x2 %0, %1, %2, %0;" : "+l"(acc) : "l"(a), "l"(b));
}
__device__ __forceinline__ float2 unpack2(unsigned long long v) {
    float lo, hi;
    asm("mov.b64 {%0, %1}, %2;" : "=f"(lo), "=f"(hi) : "l"(v));
    return make_float2(lo, hi);
}

// ---------------------------------------------------------------------------
// Kernel 1: cosine cost volume, normalization deferred to store time.
// EXACT R13 version (the 25.06us base). One h-row per block, 54KB smem,
// 2 blocks/SM; grid (96, 3), 384 threads; 4w x 8d tile per thread.
// ---------------------------------------------------------------------------
__global__ __launch_bounds__(384, 2) void cost_kernel(
    const float* __restrict__ ref, const float* __restrict__ tgt,
    float* __restrict__ out)
{
    extern __shared__ float smbuf[];
    float (*r)[WF]  = reinterpret_cast<float (*)[WF]>(smbuf);            // [C][WF]
    float (*t)[TP]  = reinterpret_cast<float (*)[TP]>(smbuf + C*WF);     // [C][TP]
    float* part_r   = smbuf + C*WF + C*TP;                               // [192]
    float* part_t   = part_r + WF;                                       // [192]
    float* ir       = part_t + WF;                                       // [WF]
    float* itp      = ir + WF;                                           // [TP]

    const int h   = blockIdx.x;
    const int by  = blockIdx.y;
    const int tid = threadIdx.x;

    if (tid < 128) {
        int c = tid / 4;
        int q = tid % 4;
        *reinterpret_cast<float4*>(&t[c][q*4]) = make_float4(0.f,0.f,0.f,0.f);
    } else if (tid < 132) {
        int q = tid - 128;
        *reinterpret_cast<float4*>(&itp[q*4]) = make_float4(0.f,0.f,0.f,0.f);
    }

    #pragma unroll
    for (int j = 0; j < 4; j++) {
        int k  = tid + j*384;
        int c  = k / 48;
        int kk = k % 48;
        *reinterpret_cast<float4*>(&r[c][kk*4]) =
            *reinterpret_cast<const float4*>(ref + c*CHW + h*WF + kk*4);
        *reinterpret_cast<float4*>(&t[c][16 + kk*4]) =
            *reinterpret_cast<const float4*>(tgt + c*CHW + h*WF + kk*4);
    }
    __syncthreads();

    {
        int w    = tid % WF;
        int half = tid / WF;
        float sr = 0.f, st = 0.f;
        int cbase = half * 16;
        #pragma unroll
        for (int c = 0; c < 16; c++) {
            float a = r[cbase + c][w];      sr = fmaf(a, a, sr);
            float b = t[cbase + c][16 + w]; st = fmaf(b, b, st);
        }
        if (half) { part_r[w] = sr; part_t[w] = st; }
        __syncthreads();
        if (!half) {
            ir[w]       = rsqrtf(sr + part_r[w] + 1e-12f);
            itp[16 + w] = rsqrtf(st + part_t[w] + 1e-12f);
        }
    }
    __syncthreads();

    const int wq = tid % 48;
    const int dq = tid / 48;
    const int w0 = wq * 4;
    const int d0 = 8 * (3*dq + by);

    unsigned long long axy0[8], azw0[8];
    #pragma unroll
    for (int i = 0; i < 8; i++) { axy0[i] = 0ULL; azw0[i] = 0ULL; }

    const int pb = 16 + w0 - d0 - 8;

    if (w0 - d0 >= 0) {
        for (int c = 0; c < C; c++) {
            float4 a  = *reinterpret_cast<const float4*>(&r[c][w0]);
            float4 v0 = *reinterpret_cast<const float4*>(&t[c][pb]);
            float4 v1 = *reinterpret_cast<const float4*>(&t[c][pb + 4]);
            float4 v2 = *reinterpret_cast<const float4*>(&t[c][pb + 8]);
            float e[12] = {v0.x, v0.y, v0.z, v0.w,
                           v1.x, v1.y, v1.z, v1.w,
                           v2.x, v2.y, v2.z, v2.w};
            unsigned long long pxy = pack2(a.x, a.y);
            unsigned long long pzw = pack2(a.z, a.w);
            #pragma unroll
            for (int j = 1; j <= 10; j++) {
                unsigned long long P = pack2(e[j], e[j+1]);
                if (j <= 8) fma2(axy0[8 - j], pxy, P);
                if (j >= 3) fma2(azw0[10 - j], pzw, P);
            }
        }
        float4 irq = *reinterpret_cast<const float4*>(&ir[w0]);
        float4 s0 = *reinterpret_cast<const float4*>(&itp[pb]);
        float4 s1 = *reinterpret_cast<const float4*>(&itp[pb + 4]);
        float4 s2 = *reinterpret_cast<const float4*>(&itp[pb + 8]);
        float e[12] = {s0.x, s0.y, s0.z, s0.w,
                       s1.x, s1.y, s1.z, s1.w,
                       s2.x, s2.y, s2.z, s2.w};
        #pragma unroll
        for (int i = 0; i < 8; i++) {
            float2 xy = unpack2(axy0[i]);
            float2 zw = unpack2(azw0[i]);
            float4 o;
            o.x = xy.x * irq.x * e[8  - i];
            o.y = xy.y * irq.y * e[9  - i];
            o.z = zw.x * irq.z * e[10 - i];
            o.w = zw.y * irq.w * e[11 - i];
            *reinterpret_cast<float4*>(&out[((d0 + i)*HF + h)*WF + w0]) = o;
        }
    } else {
        float4 z = make_float4(0.f, 0.f, 0.f, 0.f);
        #pragma unroll
        for (int i = 0; i < 8; i++)
            *reinterpret_cast<float4*>(&out[((d0 + i)*HF + h)*WF + w0]) = z;
    }
}

// ---------------------------------------------------------------------------
// Kernel 2: fused trilinear upsample + argmax + clamp(.,1).
// Same math as the R7 pred, but the serial argmax chain is replaced with an
// EXACT (value,index) pairwise-max TREE: per 8-candidate chunk a depth-3
// tree of independent merges, then one cross-chunk merge. Merge keeps the
// earlier candidate on ties ("later wins only on strict >"), so the ordered
// list (s0-exact, e=0..47, s47-exact) reproduces first-occurrence semantics
// bit-exactly. Critical path drops from 48 dependent compare stages to ~9.
// ---------------------------------------------------------------------------
#define SSTR 52

// later candidate (bv,bi) replaces (av,ai) only on strict >
#define MRG(av, ai, bv, bi) do { if ((bv) > (av)) { (av) = (bv); (ai) = (bi); } } while (0)

__device__ __forceinline__ float bilin1(const float* __restrict__ c00,
                                        const float* __restrict__ c01,
                                        const float* __restrict__ c10,
                                        const float* __restrict__ c11,
                                        int d, float fw, float fh)
{
    float t0 = fmaf(fw, c01[d] - c00[d], c00[d]);
    float t1 = fmaf(fw, c11[d] - c10[d], c10[d]);
    return fmaf(fh, t1 - t0, t0);
}

__device__ __forceinline__ void chunk8(const float* __restrict__ c00,
                                       const float* __restrict__ c01,
                                       const float* __restrict__ c10,
                                       const float* __restrict__ c11,
                                       int dbase, float fw, float fh,
                                       float* __restrict__ s)
{
    #pragma unroll
    for (int half = 0; half < 2; half++) {
        float4 v00 = *reinterpret_cast<const float4*>(c00 + dbase + half*4);
        float4 v01 = *reinterpret_cast<const float4*>(c01 + dbase + half*4);
        float4 v10 = *reinterpret_cast<const float4*>(c10 + dbase + half*4);
        float4 v11 = *reinterpret_cast<const float4*>(c11 + dbase + half*4);
        float t0, t1;
        t0 = fmaf(fw, v01.x - v00.x, v00.x);
        t1 = fmaf(fw, v11.x - v10.x, v10.x);
        s[half*4+0] = fmaf(fh, t1 - t0, t0);
        t0 = fmaf(fw, v01.y - v00.y, v00.y);
        t1 = fmaf(fw, v11.y - v10.y, v10.y);
        s[half*4+1] = fmaf(fh, t1 - t0, t0);
        t0 = fmaf(fw, v01.z - v00.z, v00.z);
        t1 = fmaf(fw, v11.z - v10.z, v10.z);
        s[half*4+2] = fmaf(fh, t1 - t0, t0);
        t0 = fmaf(fw, v01.w - v00.w, v00.w);
        t1 = fmaf(fw, v11.w - v10.w, v10.w);
        s[half*4+3] = fmaf(fh, t1 - t0, t0);
    }
}

// Exact depth-3 tree reduce of 8 ordered (value,index) candidates, then merge
// into the running (earlier) global best.
__device__ __forceinline__ void tree8(const float* __restrict__ v,
                                      const int* __restrict__ idx,
                                      float& best, int& bestE)
{
    float v0 = v[0]; int i0 = idx[0];
    float v1 = v[2]; int i1 = idx[2];
    float v2 = v[4]; int i2 = idx[4];
    float v3 = v[6]; int i3 = idx[6];
    MRG(v0, i0, v[1], idx[1]);
    MRG(v1, i1, v[3], idx[3]);
    MRG(v2, i2, v[5], idx[5]);
    MRG(v3, i3, v[7], idx[7]);
    MRG(v0, i0, v1, i1);
    MRG(v2, i2, v3, i3);
    MRG(v0, i0, v2, i2);
    MRG(best, bestE, v0, i0);
}

__global__ __launch_bounds__(256) void pred_kernel(
    const float* __restrict__ cost, float* __restrict__ pred)
{
    __shared__ float sc[4][10][SSTR];
    const int tx = threadIdx.x, ty = threadIdx.y;
    const int tid = ty*32 + tx;
    const int hb = 2*(int)blockIdx.y - 1;
    const int wb = 8*(int)blockIdx.x - 1;

    #pragma unroll
    for (int it = 0; it < 8; it++) {
        int i = tid + it * 256;
        if (i < 4*10*ND) {
            int wc = i % 10;
            int hr = (i / 10) % 4;
            int d  = i / 40;
            int hh = min(max(hb + hr, 0), HF - 1);
            int ww = min(max(wb + wc, 0), WF - 1);
            sc[hr][wc][d] = cost[(d*HF + hh)*WF + ww];
        }
    }
    __syncthreads();

    const int wo = blockIdx.x*32 + tx;
    const int ho = blockIdx.y*8 + ty;

    float xh = fminf(fmaxf(0.25f*(float)ho - 0.375f, 0.f), (float)(HF - 1));
    int   h0 = min((int)xh, HF - 2);
    float fh = xh - (float)h0;
    float xw = fminf(fmaxf(0.25f*(float)wo - 0.375f, 0.f), (float)(WF - 1));
    int   w0 = min((int)xw, WF - 2);
    float fw = xw - (float)w0;

    const int lh = h0 - hb;
    const int lw = w0 - wb;
    const float* c00 = &sc[lh][lw][0];
    const float* c01 = &sc[lh][lw+1][0];
    const float* c10 = &sc[lh+1][lw][0];
    const float* c11 = &sc[lh+1][lw+1][0];

    float sA[8], sB[8];
    float best = -3.0e38f;
    int bestE  = -1;

    // chunk 0: candidates [s0-exact(idx -1), e=0..6]
    chunk8(c00, c01, c10, c11, 0, fw, fh, sA);
    {
        float cv[8]; int ci[8];
        cv[0] = 8.0f * sA[0];                           ci[0] = -1;
        cv[1] = fmaf(7.0f, sA[0], sA[1]);               ci[1] = 0;
        #pragma unroll
        for (int e = 1; e < 7; e++) {
            cv[e+1] = fmaf(7.0f, sA[e], fmaxf(sA[e-1], sA[e+1]));
            ci[e+1] = e;
        }
        best = cv[0]; bestE = ci[0];                    // seed with earliest
        float dummy = cv[0]; int dummyi = ci[0];
        (void)dummy; (void)dummyi;
        // tree over items 1..7 merged into seed: reuse tree8 on full 8
        tree8(cv, ci, best, bestE);
    }

    // chunks 1..5: candidates [e=8q-1 .. 8q+6]
    #pragma unroll
    for (int q = 1; q < 6; q++) {
        float* sP = (q & 1) ? sA : sB;   // previous chunk buffer
        float* sN = (q & 1) ? sB : sA;   // new chunk buffer
        chunk8(c00, c01, c10, c11, q*8, fw, fh, sN);
        float cv[8]; int ci[8];
        cv[0] = fmaf(7.0f, sP[7], fmaxf(sP[6], sN[0])); ci[0] = 8*q - 1;
        cv[1] = fmaf(7.0f, sN[0], fmaxf(sP[7], sN[1])); ci[1] = 8*q;
        #pragma unroll
        for (int j = 1; j < 7; j++) {
            cv[j+1] = fmaf(7.0f, sN[j], fmaxf(sN[j-1], sN[j+1]));
            ci[j+1] = 8*q + j;
        }
        tree8(cv, ci, best, bestE);
    }

    // final: e=47 candidate, then s47-exact (idx 48, last in priority order)
    // after q=5 the newest chunk (s[40..47]) is in sB
    {
        float c47 = fmaf(7.0f, sB[7], sB[6]);
        MRG(best, bestE, c47, 47);
        float s47x8 = 8.0f * sB[7];
        MRG(best, bestE, s47x8, 48);
    }

    int k;
    if (bestE == 48) {
        k = 190;                            // exact sample s[47]
    } else if (bestE < 0) {
        k = 0;                              // exact sample s[0]
    } else {
        float smL = -3.0e38f, smR = -3.0e38f;
        if (bestE > 0)      smL = bilin1(c00, c01, c10, c11, bestE - 1, fw, fh);
        if (bestE < ND - 1) smR = bilin1(c00, c01, c10, c11, bestE + 1, fw, fh);
        k = 4*bestE + 1 + ((smR > smL) ? 1 : 0);   // tie -> left (smaller k)
    }
    k = max(k, 1);
    pred[ho*WOUT + wo] = (float)k;
}

// ---------------------------------------------------------------------------
extern "C" void kernel_launch(void* const* d_in, const int* in_sizes, int n_in,
                              void* d_out, int out_size)
{
    const float* left  = (const float*)d_in[0];
    const float* right = (const float*)d_in[1];
    float* out = (float*)d_out;

    const int smem_bytes =
        (C*WF + C*TP + WF + WF + WF + TP) * (int)sizeof(float);   // ~54 KB
    cudaFuncSetAttribute(cost_kernel,
                         cudaFuncAttributeMaxDynamicSharedMemorySize, smem_bytes);

    dim3 g1(HF, 3), b1(384);
    cost_kernel<<<g1, b1, smem_bytes>>>(left, right, out);

    dim3 g2(WOUT/32, HOUT/8), b2(32, 8);
    pred_kernel<<<g2, b2>>>(out, out + COST_ELEMS);
}

// round 16
// speedup vs baseline: 1.1124x; 1.0694x over previous
#include <cuda_runtime.h>

#define C   32
#define HF  96
#define WF  192
#define DD  192
#define HOUT 384
#define WOUT 768
#define ND  48
#define CHW (HF*WF)
#define COST_ELEMS (DD*HF*WF)
#define TP  (WF + 16)          // padded t/it rows: 16 zero floats before idx 0

// ---------------------------------------------------------------------------
// Kernel 1: cosine cost volume, normalization deferred to store time.
// R13 shape (one h-row/block, 54KB smem, grid (96,3), 384 threads) with:
//  - scalar FFMA inner loop (no f32x2 packing -> no alu-pipe MOV tax)
//  - __launch_bounds__(384,3): regs <= 55 -> 3 blocks/SM (36 warps), hiding
//    the LDS/LDG latency that capped issue at ~45% in earlier captures.
// out[d,h,w] = (sum_c r[c,w]*t[c,w-d]) * ir[w] * it[w-d]; zero-padded t/it
// keep exact zeros for w < d with a single branch-free code path.
// ---------------------------------------------------------------------------
__global__ __launch_bounds__(384, 3) void cost_kernel(
    const float* __restrict__ ref, const float* __restrict__ tgt,
    float* __restrict__ out)
{
    extern __shared__ float smbuf[];
    float (*r)[WF]  = reinterpret_cast<float (*)[WF]>(smbuf);            // [C][WF]
    float (*t)[TP]  = reinterpret_cast<float (*)[TP]>(smbuf + C*WF);     // [C][TP]
    float* part_r   = smbuf + C*WF + C*TP;                               // [192]
    float* part_t   = part_r + WF;                                       // [192]
    float* ir       = part_t + WF;                                       // [WF]
    float* itp      = ir + WF;                                           // [TP]

    const int h   = blockIdx.x;          // h-row 0..95
    const int by  = blockIdx.y;          // 0..2
    const int tid = threadIdx.x;         // 0..383

    // zero pads: t pad = C*16 floats (128 f4), itp pad = 16 floats (4 f4)
    if (tid < 128) {
        int c = tid / 4;
        int q = tid % 4;
        *reinterpret_cast<float4*>(&t[c][q*4]) = make_float4(0.f,0.f,0.f,0.f);
    } else if (tid < 132) {
        int q = tid - 128;
        *reinterpret_cast<float4*>(&itp[q*4]) = make_float4(0.f,0.f,0.f,0.f);
    }

    // vectorized loads: 1536 float4 per tensor (32 c x 48 quads)
    #pragma unroll
    for (int j = 0; j < 4; j++) {
        int k  = tid + j*384;            // 0..1535
        int c  = k / 48;
        int kk = k % 48;
        *reinterpret_cast<float4*>(&r[c][kk*4]) =
            *reinterpret_cast<const float4*>(ref + c*CHW + h*WF + kk*4);
        *reinterpret_cast<float4*>(&t[c][16 + kk*4]) =
            *reinterpret_cast<const float4*>(tgt + c*CHW + h*WF + kk*4);
    }
    __syncthreads();

    // inverse norms: 192 columns x 2 half-c partials (all 12 warps active)
    {
        int w    = tid % WF;
        int half = tid / WF;             // 0 or 1
        float sr = 0.f, st = 0.f;
        int cbase = half * 16;
        #pragma unroll
        for (int c = 0; c < 16; c++) {
            float a = r[cbase + c][w];      sr = fmaf(a, a, sr);
            float b = t[cbase + c][16 + w]; st = fmaf(b, b, st);
        }
        if (half) { part_r[w] = sr; part_t[w] = st; }
        __syncthreads();
        if (!half) {
            ir[w]       = rsqrtf(sr + part_r[w] + 1e-12f);
            itp[16 + w] = rsqrtf(st + part_t[w] + 1e-12f);
        }
    }
    __syncthreads();

    // one 4w x 8d tile per thread: 48 wq x 8 dq = 384 tiles
    const int wq = tid % 48;
    const int dq = tid / 48;             // 0..7
    const int w0 = wq * 4;
    const int d0 = 8 * (3*dq + by);      // octs 0..23 (triangle-balanced)

    float4 acc[8];
    #pragma unroll
    for (int i = 0; i < 8; i++) acc[i] = make_float4(0.f, 0.f, 0.f, 0.f);

    const int pb = 16 + w0 - d0 - 8;     // padded window base (mult of 4)

    if (w0 - d0 >= 0) {
        for (int c = 0; c < C; c++) {
            float4 a  = *reinterpret_cast<const float4*>(&r[c][w0]);
            float4 v0 = *reinterpret_cast<const float4*>(&t[c][pb]);
            float4 v1 = *reinterpret_cast<const float4*>(&t[c][pb + 4]);
            float4 v2 = *reinterpret_cast<const float4*>(&t[c][pb + 8]);
            float e[12] = {v0.x, v0.y, v0.z, v0.w,
                           v1.x, v1.y, v1.z, v1.w,
                           v2.x, v2.y, v2.z, v2.w};
            #pragma unroll
            for (int i = 0; i < 8; i++) {
                acc[i].x = fmaf(a.x, e[8  - i], acc[i].x);  // w=w0,   d=d0+i
                acc[i].y = fmaf(a.y, e[9  - i], acc[i].y);  // w=w0+1
                acc[i].z = fmaf(a.z, e[10 - i], acc[i].z);  // w=w0+2
                acc[i].w = fmaf(a.w, e[11 - i], acc[i].w);  // w=w0+3
            }
        }
        // deferred normalization at store: out = acc * ir[w] * it[w-d]
        float4 irq = *reinterpret_cast<const float4*>(&ir[w0]);
        float4 s0 = *reinterpret_cast<const float4*>(&itp[pb]);
        float4 s1 = *reinterpret_cast<const float4*>(&itp[pb + 4]);
        float4 s2 = *reinterpret_cast<const float4*>(&itp[pb + 8]);
        float e[12] = {s0.x, s0.y, s0.z, s0.w,
                       s1.x, s1.y, s1.z, s1.w,
                       s2.x, s2.y, s2.z, s2.w};
        #pragma unroll
        for (int i = 0; i < 8; i++) {
            float4 o;
            o.x = acc[i].x * irq.x * e[8  - i];
            o.y = acc[i].y * irq.y * e[9  - i];
            o.z = acc[i].z * irq.z * e[10 - i];
            o.w = acc[i].w * irq.w * e[11 - i];
            *reinterpret_cast<float4*>(&out[((d0 + i)*HF + h)*WF + w0]) = o;
        }
    } else {
        float4 z = make_float4(0.f, 0.f, 0.f, 0.f);
        #pragma unroll
        for (int i = 0; i < 8; i++)
            *reinterpret_cast<float4*>(&out[((d0 + i)*HF + h)*WF + w0]) = z;
    }
}

// ---------------------------------------------------------------------------
// Kernel 2: fused trilinear upsample + argmax + clamp(.,1).
// EXACT R7/R12/R13 version (the consistently-best pred, ~13.7us).
// ---------------------------------------------------------------------------
#define SSTR 52

__device__ __forceinline__ float bilin1(const float* __restrict__ c00,
                                        const float* __restrict__ c01,
                                        const float* __restrict__ c10,
                                        const float* __restrict__ c11,
                                        int d, float fw, float fh)
{
    float t0 = fmaf(fw, c01[d] - c00[d], c00[d]);
    float t1 = fmaf(fw, c11[d] - c10[d], c10[d]);
    return fmaf(fh, t1 - t0, t0);
}

__device__ __forceinline__ void chunk8(const float* __restrict__ c00,
                                       const float* __restrict__ c01,
                                       const float* __restrict__ c10,
                                       const float* __restrict__ c11,
                                       int dbase, float fw, float fh,
                                       float* __restrict__ s)
{
    #pragma unroll
    for (int half = 0; half < 2; half++) {
        float4 v00 = *reinterpret_cast<const float4*>(c00 + dbase + half*4);
        float4 v01 = *reinterpret_cast<const float4*>(c01 + dbase + half*4);
        float4 v10 = *reinterpret_cast<const float4*>(c10 + dbase + half*4);
        float4 v11 = *reinterpret_cast<const float4*>(c11 + dbase + half*4);
        float t0, t1;
        t0 = fmaf(fw, v01.x - v00.x, v00.x);
        t1 = fmaf(fw, v11.x - v10.x, v10.x);
        s[half*4+0] = fmaf(fh, t1 - t0, t0);
        t0 = fmaf(fw, v01.y - v00.y, v00.y);
        t1 = fmaf(fw, v11.y - v10.y, v10.y);
        s[half*4+1] = fmaf(fh, t1 - t0, t0);
        t0 = fmaf(fw, v01.z - v00.z, v00.z);
        t1 = fmaf(fw, v11.z - v10.z, v10.z);
        s[half*4+2] = fmaf(fh, t1 - t0, t0);
        t0 = fmaf(fw, v01.w - v00.w, v00.w);
        t1 = fmaf(fw, v11.w - v10.w, v10.w);
        s[half*4+3] = fmaf(fh, t1 - t0, t0);
    }
}

__device__ __forceinline__ void scan_head(const float* __restrict__ s,
                                          float& best, int& bestE)
{
    #pragma unroll
    for (int e = 0; e < 7; e++) {
        float nb = (e == 0) ? s[1] : fmaxf(s[e-1], s[e+1]);
        float cand = fmaf(7.0f, s[e], nb);
        if (cand > best) { best = cand; bestE = e; }
    }
}

__device__ __forceinline__ void scan_mid(const float* __restrict__ p,
                                         const float* __restrict__ c,
                                         int qb, float& best, int& bestE)
{
    {   float nb = fmaxf(p[6], c[0]);
        float cand = fmaf(7.0f, p[7], nb);
        if (cand > best) { best = cand; bestE = qb - 1; } }
    {   float nb = fmaxf(p[7], c[1]);
        float cand = fmaf(7.0f, c[0], nb);
        if (cand > best) { best = cand; bestE = qb; } }
    #pragma unroll
    for (int j = 1; j < 7; j++) {
        float nb = fmaxf(c[j-1], c[j+1]);
        float cand = fmaf(7.0f, c[j], nb);
        if (cand > best) { best = cand; bestE = qb + j; }
    }
}

__global__ __launch_bounds__(256) void pred_kernel(
    const float* __restrict__ cost, float* __restrict__ pred)
{
    __shared__ float sc[4][10][SSTR];
    const int tx = threadIdx.x, ty = threadIdx.y;
    const int tid = ty*32 + tx;
    const int hb = 2*(int)blockIdx.y - 1;
    const int wb = 8*(int)blockIdx.x - 1;

    #pragma unroll
    for (int it = 0; it < 8; it++) {
        int i = tid + it * 256;
        if (i < 4*10*ND) {
            int wc = i % 10;
            int hr = (i / 10) % 4;
            int d  = i / 40;
            int hh = min(max(hb + hr, 0), HF - 1);
            int ww = min(max(wb + wc, 0), WF - 1);
            sc[hr][wc][d] = cost[(d*HF + hh)*WF + ww];
        }
    }
    __syncthreads();

    const int wo = blockIdx.x*32 + tx;
    const int ho = blockIdx.y*8 + ty;

    float xh = fminf(fmaxf(0.25f*(float)ho - 0.375f, 0.f), (float)(HF - 1));
    int   h0 = min((int)xh, HF - 2);
    float fh = xh - (float)h0;
    float xw = fminf(fmaxf(0.25f*(float)wo - 0.375f, 0.f), (float)(WF - 1));
    int   w0 = min((int)xw, WF - 2);
    float fw = xw - (float)w0;

    const int lh = h0 - hb;
    const int lw = w0 - wb;
    const float* c00 = &sc[lh][lw][0];
    const float* c01 = &sc[lh][lw+1][0];
    const float* c10 = &sc[lh+1][lw][0];
    const float* c11 = &sc[lh+1][lw+1][0];

    float sA[8], sB[8];
    float best;
    int bestE = -1;                      // -1 => k = 0

    chunk8(c00, c01, c10, c11, 0, fw, fh, sA);
    best = 8.0f * sA[0];                 // exact sample s[0] (scaled)
    scan_head(sA, best, bestE);

    chunk8(c00, c01, c10, c11,  8, fw, fh, sB); scan_mid(sA, sB,  8, best, bestE);
    chunk8(c00, c01, c10, c11, 16, fw, fh, sA); scan_mid(sB, sA, 16, best, bestE);
    chunk8(c00, c01, c10, c11, 24, fw, fh, sB); scan_mid(sA, sB, 24, best, bestE);
    chunk8(c00, c01, c10, c11, 32, fw, fh, sA); scan_mid(sB, sA, 32, best, bestE);
    chunk8(c00, c01, c10, c11, 40, fw, fh, sB); scan_mid(sA, sB, 40, best, bestE);

    {   // e = 47
        float nb = sB[6];
        float cand = fmaf(7.0f, sB[7], nb);
        if (cand > best) { best = cand; bestE = 47; }
    }
    float s47 = sB[7];

    int k;
    if (8.0f * s47 > best) {
        k = 4*(ND-1) + 2;                   // 190: exact sample s[47]
    } else if (bestE < 0) {
        k = 0;
    } else {
        float smL = -3.0e38f, smR = -3.0e38f;
        if (bestE > 0)      smL = bilin1(c00, c01, c10, c11, bestE - 1, fw, fh);
        if (bestE < ND - 1) smR = bilin1(c00, c01, c10, c11, bestE + 1, fw, fh);
        k = 4*bestE + 1 + ((smR > smL) ? 1 : 0);   // tie -> left (smaller k)
    }
    k = max(k, 1);
    pred[ho*WOUT + wo] = (float)k;
}

// ---------------------------------------------------------------------------
extern "C" void kernel_launch(void* const* d_in, const int* in_sizes, int n_in,
                              void* d_out, int out_size)
{
    const float* left  = (const float*)d_in[0];
    const float* right = (const float*)d_in[1];
    float* out = (float*)d_out;

    const int smem_bytes =
        (C*WF + C*TP + WF + WF + WF + TP) * (int)sizeof(float);   // ~54 KB
    cudaFuncSetAttribute(cost_kernel,
                         cudaFuncAttributeMaxDynamicSharedMemorySize, smem_bytes);

    dim3 g1(HF, 3), b1(384);
    cost_kernel<<<g1, b1, smem_bytes>>>(left, right, out);

    dim3 g2(WOUT/32, HOUT/8), b2(32, 8);
    pred_kernel<<<g2, b2>>>(out, out + COST_ELEMS);
}